// round 12
// baseline (speedup 1.0000x reference)
#include <cuda_runtime.h>

// Problem constants
#define H 512
#define W 512
#define HW (H * W)
#define NC 48                 // 16 batch * 3 channels
#define OH 171
#define OW 171
#define TOTAL (NC * OH * OW)  // 1,403,568 output pixels
#define IW 170                // interior ox/oy in 1..170
#define NI (NC * IW * IW)     // 1,387,200 interior pixels
#define NE (NC * (OH + IW))   // 16,368 edge pixels (oy==0 row + ox==0 col)
#define NBLOCKS 1184          // measured-optimal grid (sweep 888/1184/1776)
#define STRIDE (NBLOCKS * 256)        // 303,104
#define D_OX   (STRIDE % IW)          // 164
#define D_T    (STRIDE / IW)          // 1782
#define D_OY   (D_T % IW)             // 82
#define D_PL   (D_T / IW)             // 10

__device__ float        g_partial = 0.0f;
__device__ unsigned int g_count   = 0;

__global__ void __launch_bounds__(256, 6) ssim_kernel(
    const float* __restrict__ img1,
    const float* __restrict__ img2,
    const float* __restrict__ window,
    float* __restrict__ out)
{
    const float C1 = 0.0001f;   // 0.01^2
    const float C2 = 0.0009f;   // 0.03^2

    // 3x3 gaussian window (identical per channel) — broadcast, L1-resident
    float w[9];
    #pragma unroll
    for (int i = 0; i < 9; i++) w[i] = __ldg(window + i);

    float acc = 0.0f;
    const int gtid = blockIdx.x * blockDim.x + threadIdx.x;

    // ---- hot loop: interior pixels (ox,oy in 1..170), branch-free loads.
    // Index decomposition is done once; per-iteration update is add+carry
    // (no integer division in the loop).
    {
        int idx   = gtid;
        int oxm   = idx % IW;          // ox-1 in 0..169
        int t     = idx / IW;
        int oym   = t % IW;            // oy-1 in 0..169
        int plane = t / IW;

        while (idx < NI) {
            const int ix = 3 * oxm + 2;    // = 3*ox - 1, >= 2
            const int iy = 3 * oym + 2;    // = 3*oy - 1, >= 2 (max 509+2=511)

            const float* __restrict__ q1 = img1 + (size_t)plane * HW + iy * W + ix;
            const float* __restrict__ q2 = img2 + (size_t)plane * HW + iy * W + ix;

            float a[9], b[9];
            #pragma unroll
            for (int r = 0; r < 3; r++)
                #pragma unroll
                for (int c = 0; c < 3; c++)
                    a[r * 3 + c] = __ldg(q1 + r * W + c);
            #pragma unroll
            for (int r = 0; r < 3; r++)
                #pragma unroll
                for (int c = 0; c < 3; c++)
                    b[r * 3 + c] = __ldg(q2 + r * W + c);

            float mu1 = 0.f, mu2 = 0.f, s11 = 0.f, s22 = 0.f, s12 = 0.f;
            #pragma unroll
            for (int k = 0; k < 9; k++) {
                const float wa = w[k] * a[k];
                const float wb = w[k] * b[k];
                mu1 += wa;
                mu2 += wb;
                s11 = fmaf(wa, a[k], s11);
                s22 = fmaf(wb, b[k], s22);
                s12 = fmaf(wa, b[k], s12);
            }

            const float m11 = mu1 * mu1;
            const float m22 = mu2 * mu2;
            const float m12 = mu1 * mu2;
            const float num = (2.0f * m12 + C1) * (2.0f * (s12 - m12) + C2);
            const float den = (m11 + m22 + C1) * ((s11 - m11) + (s22 - m22) + C2);
            acc += __fdividef(num, den);

            // incremental index update: idx += STRIDE
            idx += STRIDE;
            oxm += D_OX;
            int tc = D_T;
            if (oxm >= IW) { oxm -= IW; tc += 1; }     // tc in {1782,1783}
            oym += tc - D_PL * IW;                      // += 82 or 83
            plane += D_PL;
            if (oym >= IW) { oym -= IW; plane += 1; }
        }
    }

    // ---- cold loop: edge pixels (oy==0 full row, then ox==0 column) ----
    for (int e = gtid; e < NE; e += STRIDE) {
        const int plane = e / (OH + IW);
        const int r0    = e % (OH + IW);
        int ox, oy;
        if (r0 < OH) { oy = 0;        ox = r0; }
        else         { ox = 0;        oy = r0 - IW; }   // oy = 1..170

        const int ix = 3 * ox - 1;
        const int iy = 3 * oy - 1;
        const float* __restrict__ p1 = img1 + (size_t)plane * HW;
        const float* __restrict__ p2 = img2 + (size_t)plane * HW;

        float mu1 = 0.f, mu2 = 0.f, s11 = 0.f, s22 = 0.f, s12 = 0.f;
        #pragma unroll
        for (int r = 0; r < 3; r++) {
            #pragma unroll
            for (int c = 0; c < 3; c++) {
                const int row = iy + r;
                const int col = ix + c;
                const bool ok = (row >= 0) && (col >= 0);
                const float a = ok ? __ldg(p1 + row * W + col) : 0.0f;
                const float b = ok ? __ldg(p2 + row * W + col) : 0.0f;
                const float wt = w[r * 3 + c];
                const float wa = wt * a;
                const float wb = wt * b;
                mu1 += wa;
                mu2 += wb;
                s11 = fmaf(wa, a, s11);
                s22 = fmaf(wb, b, s22);
                s12 = fmaf(wa, b, s12);
            }
        }

        const float m11 = mu1 * mu1;
        const float m22 = mu2 * mu2;
        const float m12 = mu1 * mu2;
        const float num = (2.0f * m12 + C1) * (2.0f * (s12 - m12) + C2);
        const float den = (m11 + m22 + C1) * ((s11 - m11) + (s22 - m22) + C2);
        acc += __fdividef(num, den);
    }

    // ---- block reduction: warp shuffle -> smem -> warp0 -> one atomic ----
    #pragma unroll
    for (int o = 16; o > 0; o >>= 1)
        acc += __shfl_down_sync(0xffffffffu, acc, o);

    __shared__ float wsum[8];
    const int lane = threadIdx.x & 31;
    const int wid  = threadIdx.x >> 5;
    if (lane == 0) wsum[wid] = acc;
    __syncthreads();

    if (wid == 0) {
        acc = (lane < 8) ? wsum[lane] : 0.0f;
        #pragma unroll
        for (int o = 4; o > 0; o >>= 1)
            acc += __shfl_down_sync(0xffffffffu, acc, o);
        if (lane == 0)
            atomicAdd(&g_partial, acc * (1.0f / (float)TOTAL));
    }

    // ---- last block publishes result, resets scratch (graph-replay safe) ----
    __shared__ bool is_last;
    if (threadIdx.x == 0) {
        __threadfence();
        const unsigned prev = atomicAdd(&g_count, 1u);
        is_last = (prev == (unsigned)(gridDim.x - 1));
    }
    __syncthreads();
    if (is_last && threadIdx.x == 0) {
        *out      = g_partial;
        g_partial = 0.0f;
        g_count   = 0;
    }
}

extern "C" void kernel_launch(void* const* d_in, const int* in_sizes, int n_in,
                              void* d_out, int out_size)
{
    const float* img1   = (const float*)d_in[0];
    const float* img2   = (const float*)d_in[1];
    const float* window = (const float*)d_in[2];
    float* out = (float*)d_out;

    ssim_kernel<<<NBLOCKS, 256>>>(img1, img2, window, out);
}

// round 13
// speedup vs baseline: 1.0019x; 1.0019x over previous
#include <cuda_runtime.h>

// Problem constants
#define H 512
#define W 512
#define HW (H * W)
#define NC 48                 // 16 batch * 3 channels
#define OH 171
#define OW 171
#define TOTAL (NC * OH * OW)  // 1,403,568 output pixels
#define IW 170                // interior ox/oy in 1..170
#define NI (NC * IW * IW)     // 1,387,200 interior pixels
#define NE (NC * (OH + IW))   // 16,368 edge pixels (oy==0 row + ox==0 col)
#define TPB 128               // finer block granularity: 12 resident blocks/SM @40regs
#define NBLOCKS 2368          // same total threads as measured-optimal 1184x256

__device__ float        g_partial = 0.0f;
__device__ unsigned int g_count   = 0;

__global__ void __launch_bounds__(TPB, 12) ssim_kernel(
    const float* __restrict__ img1,
    const float* __restrict__ img2,
    const float* __restrict__ window,
    float* __restrict__ out)
{
    const float C1 = 0.0001f;   // 0.01^2
    const float C2 = 0.0009f;   // 0.03^2

    // 3x3 gaussian window (identical per channel) — broadcast, L1-resident
    float w[9];
    #pragma unroll
    for (int i = 0; i < 9; i++) w[i] = __ldg(window + i);

    float acc = 0.0f;
    const int gtid   = blockIdx.x * TPB + threadIdx.x;
    const int stride = NBLOCKS * TPB;

    // ---- hot loop: interior pixels only (ox,oy in 1..170) — branch-free ----
    for (int idx = gtid; idx < NI; idx += stride) {
        const int ox    = 1 + idx % IW;
        const int t     = idx / IW;
        const int oy    = 1 + t % IW;
        const int plane = t / IW;

        const int ix = 3 * ox - 1;   // >= 2
        const int iy = 3 * oy - 1;   // >= 2, high side 511 max

        const float* __restrict__ q1 = img1 + (size_t)plane * HW + iy * W + ix;
        const float* __restrict__ q2 = img2 + (size_t)plane * HW + iy * W + ix;

        float a[9], b[9];
        #pragma unroll
        for (int r = 0; r < 3; r++)
            #pragma unroll
            for (int c = 0; c < 3; c++)
                a[r * 3 + c] = __ldg(q1 + r * W + c);
        #pragma unroll
        for (int r = 0; r < 3; r++)
            #pragma unroll
            for (int c = 0; c < 3; c++)
                b[r * 3 + c] = __ldg(q2 + r * W + c);

        float mu1 = 0.f, mu2 = 0.f, s11 = 0.f, s22 = 0.f, s12 = 0.f;
        #pragma unroll
        for (int k = 0; k < 9; k++) {
            const float wa = w[k] * a[k];
            const float wb = w[k] * b[k];
            mu1 += wa;
            mu2 += wb;
            s11 = fmaf(wa, a[k], s11);
            s22 = fmaf(wb, b[k], s22);
            s12 = fmaf(wa, b[k], s12);
        }

        const float m11 = mu1 * mu1;
        const float m22 = mu2 * mu2;
        const float m12 = mu1 * mu2;
        const float num = (2.0f * m12 + C1) * (2.0f * (s12 - m12) + C2);
        const float den = (m11 + m22 + C1) * ((s11 - m11) + (s22 - m22) + C2);
        acc += __fdividef(num, den);
    }

    // ---- cold loop: edge pixels (oy==0 full row, then ox==0 column) ----
    for (int e = gtid; e < NE; e += stride) {
        const int plane = e / (OH + IW);
        const int r0    = e % (OH + IW);
        int ox, oy;
        if (r0 < OH) { oy = 0;        ox = r0; }
        else         { ox = 0;        oy = r0 - IW; }   // oy = 1..170

        const int ix = 3 * ox - 1;
        const int iy = 3 * oy - 1;
        const float* __restrict__ p1 = img1 + (size_t)plane * HW;
        const float* __restrict__ p2 = img2 + (size_t)plane * HW;

        float mu1 = 0.f, mu2 = 0.f, s11 = 0.f, s22 = 0.f, s12 = 0.f;
        #pragma unroll
        for (int r = 0; r < 3; r++) {
            #pragma unroll
            for (int c = 0; c < 3; c++) {
                const int row = iy + r;
                const int col = ix + c;
                const bool ok = (row >= 0) && (col >= 0);
                const float a = ok ? __ldg(p1 + row * W + col) : 0.0f;
                const float b = ok ? __ldg(p2 + row * W + col) : 0.0f;
                const float wt = w[r * 3 + c];
                const float wa = wt * a;
                const float wb = wt * b;
                mu1 += wa;
                mu2 += wb;
                s11 = fmaf(wa, a, s11);
                s22 = fmaf(wb, b, s22);
                s12 = fmaf(wa, b, s12);
            }
        }

        const float m11 = mu1 * mu1;
        const float m22 = mu2 * mu2;
        const float m12 = mu1 * mu2;
        const float num = (2.0f * m12 + C1) * (2.0f * (s12 - m12) + C2);
        const float den = (m11 + m22 + C1) * ((s11 - m11) + (s22 - m22) + C2);
        acc += __fdividef(num, den);
    }

    // ---- block reduction: warp shuffle -> smem -> warp0 -> one atomic ----
    #pragma unroll
    for (int o = 16; o > 0; o >>= 1)
        acc += __shfl_down_sync(0xffffffffu, acc, o);

    __shared__ float wsum[4];   // 128 threads -> 4 warps
    const int lane = threadIdx.x & 31;
    const int wid  = threadIdx.x >> 5;
    if (lane == 0) wsum[wid] = acc;
    __syncthreads();

    if (wid == 0) {
        acc = (lane < 4) ? wsum[lane] : 0.0f;
        #pragma unroll
        for (int o = 2; o > 0; o >>= 1)
            acc += __shfl_down_sync(0xffffffffu, acc, o);
        if (lane == 0)
            atomicAdd(&g_partial, acc * (1.0f / (float)TOTAL));
    }

    // ---- last block publishes result, resets scratch (graph-replay safe) ----
    __shared__ bool is_last;
    if (threadIdx.x == 0) {
        __threadfence();
        const unsigned prev = atomicAdd(&g_count, 1u);
        is_last = (prev == (unsigned)(gridDim.x - 1));
    }
    __syncthreads();
    if (is_last && threadIdx.x == 0) {
        *out      = g_partial;
        g_partial = 0.0f;
        g_count   = 0;
    }
}

extern "C" void kernel_launch(void* const* d_in, const int* in_sizes, int n_in,
                              void* d_out, int out_size)
{
    const float* img1   = (const float*)d_in[0];
    const float* img2   = (const float*)d_in[1];
    const float* window = (const float*)d_in[2];
    float* out = (float*)d_out;

    ssim_kernel<<<NBLOCKS, TPB>>>(img1, img2, window, out);
}